// round 1
// baseline (speedup 1.0000x reference)
#include <cuda_runtime.h>
#include <math.h>

#define H 1024
#define S 32768
#define DCHUNKS 32
#define DPER (H / DCHUNKS)   // 32

// Scratch (no allocations allowed in kernel_launch)
__device__ float g_vpart[DCHUNKS * H];
__device__ float g_v[H];
__device__ float g_scores[S];
__device__ float g_stats[2];   // {gmax, inv_sum}

// ---------------------------------------------------------------------------
// v_partial[chunk][h] = sum_{d in chunk} hidden[d] * W[d*H + h]
// grid (H/128, DCHUNKS), block 128. Coalesced 512B/warp reads of W columns.
// ---------------------------------------------------------------------------
__global__ void k_matvec_partial(const float* __restrict__ hidden,
                                 const float* __restrict__ W) {
    const int h     = blockIdx.x * 128 + threadIdx.x;
    const int chunk = blockIdx.y;
    const int d0    = chunk * DPER;
    float acc = 0.0f;
#pragma unroll 8
    for (int d = 0; d < DPER; d++) {
        acc = fmaf(__ldg(&hidden[d0 + d]), __ldg(&W[(size_t)(d0 + d) * H + h]), acc);
    }
    g_vpart[chunk * H + h] = acc;
}

// ---------------------------------------------------------------------------
// v[h] = sum over chunks of v_partial — deterministic fold. grid 4, block 256.
// ---------------------------------------------------------------------------
__global__ void k_matvec_reduce() {
    const int h = blockIdx.x * 256 + threadIdx.x;
    float acc = 0.0f;
#pragma unroll
    for (int c = 0; c < DCHUNKS; c++) acc += g_vpart[c * H + h];
    g_v[h] = acc;
}

// ---------------------------------------------------------------------------
// scores[s] = enc[s] . v      (the 128 MB HBM-bound pass)
// 8 warps/block, 1 row/warp. v staged in shared as float4. float4 enc loads,
// 8 independent loads per lane (MLP=8), shfl tree reduce.
// grid S/8 = 4096, block 256.
// ---------------------------------------------------------------------------
__global__ void k_scores(const float* __restrict__ enc) {
    __shared__ float4 sv[H / 4];   // 4 KB
    const int tid  = threadIdx.x;
    const int warp = tid >> 5;
    const int lane = tid & 31;

    // cooperative load of v into shared
    sv[tid] = reinterpret_cast<const float4*>(g_v)[tid];
    __syncthreads();

    const int row = blockIdx.x * 8 + warp;
    const float4* erow = reinterpret_cast<const float4*>(enc + (size_t)row * H);

    float acc = 0.0f;
#pragma unroll
    for (int i = 0; i < 8; i++) {
        const int idx = lane + 32 * i;        // 0..255 float4s
        float4 e = __ldg(&erow[idx]);
        float4 w = sv[idx];
        acc = fmaf(e.x, w.x, acc);
        acc = fmaf(e.y, w.y, acc);
        acc = fmaf(e.z, w.z, acc);
        acc = fmaf(e.w, w.w, acc);
    }
#pragma unroll
    for (int off = 16; off > 0; off >>= 1)
        acc += __shfl_xor_sync(0xFFFFFFFFu, acc, off);
    if (lane == 0) g_scores[row] = acc;
}

// ---------------------------------------------------------------------------
// Deterministic softmax stats over 32768 scores (L2-resident). 1 block, 1024 thr.
// ---------------------------------------------------------------------------
__global__ void k_stats() {
    __shared__ float red[1024];
    const int t = threadIdx.x;

    float m = -INFINITY;
    for (int i = t; i < S; i += 1024) m = fmaxf(m, g_scores[i]);
    red[t] = m;
    __syncthreads();
    for (int s = 512; s > 0; s >>= 1) {
        if (t < s) red[t] = fmaxf(red[t], red[t + s]);
        __syncthreads();
    }
    const float gmax = red[0];
    __syncthreads();

    float sum = 0.0f;
    for (int i = t; i < S; i += 1024) sum += expf(g_scores[i] - gmax);
    red[t] = sum;
    __syncthreads();
    for (int s = 512; s > 0; s >>= 1) {
        if (t < s) red[t] += red[t + s];
        __syncthreads();
    }
    if (t == 0) {
        g_stats[0] = gmax;
        g_stats[1] = 1.0f / red[0];
    }
}

// ---------------------------------------------------------------------------
// out[s] = exp(scores[s] - gmax) * inv_sum.   grid 128, block 256.
// ---------------------------------------------------------------------------
__global__ void k_norm(float* __restrict__ out) {
    const int i = blockIdx.x * 256 + threadIdx.x;
    out[i] = expf(g_scores[i] - g_stats[0]) * g_stats[1];
}

// ---------------------------------------------------------------------------
// Inputs (metadata order): hidden[1024], encoder_outputs[32768*1024],
//                          W[1024*1024], b[1024] (b cancels in softmax).
// Output: float[32768].
// ---------------------------------------------------------------------------
extern "C" void kernel_launch(void* const* d_in, const int* in_sizes, int n_in,
                              void* d_out, int out_size) {
    const float* hidden = (const float*)d_in[0];
    const float* enc    = (const float*)d_in[1];
    const float* W      = (const float*)d_in[2];
    float* out          = (float*)d_out;

    dim3 g1(H / 128, DCHUNKS);
    k_matvec_partial<<<g1, 128>>>(hidden, W);
    k_matvec_reduce<<<H / 256, 256>>>();
    k_scores<<<S / 8, 256>>>(enc);
    k_stats<<<1, 1024>>>();
    k_norm<<<S / 256, 256>>>(out);
}

// round 2
// speedup vs baseline: 1.1062x; 1.1062x over previous
#include <cuda_runtime.h>
#include <math.h>

#define H 1024
#define S 32768
#define DCHUNKS 32
#define DPER (H / DCHUNKS)   // 32
#define NPART 32             // stats partial blocks

// Scratch (no allocations allowed in kernel_launch)
__device__ __align__(16) float g_vpart[DCHUNKS * H];
__device__ __align__(16) float g_v[H];
__device__ __align__(16) float g_scores[S];
__device__ __align__(16) float g_pmax[NPART];
__device__ __align__(16) float g_psum[NPART];

// ---------------------------------------------------------------------------
// v_partial[chunk][h] = sum_{d in chunk} hidden[d] * W[d*H + h]
// grid (H/128, DCHUNKS), block 128.
// ---------------------------------------------------------------------------
__global__ void k_matvec_partial(const float* __restrict__ hidden,
                                 const float* __restrict__ W) {
    const int h     = blockIdx.x * 128 + threadIdx.x;
    const int chunk = blockIdx.y;
    const int d0    = chunk * DPER;
    float acc = 0.0f;
#pragma unroll 8
    for (int d = 0; d < DPER; d++) {
        acc = fmaf(__ldg(&hidden[d0 + d]), __ldg(&W[(size_t)(d0 + d) * H + h]), acc);
    }
    g_vpart[chunk * H + h] = acc;
}

// ---------------------------------------------------------------------------
// v[h] = deterministic fold over chunks. grid 4, block 256.
// ---------------------------------------------------------------------------
__global__ void k_matvec_reduce() {
    const int h = blockIdx.x * 256 + threadIdx.x;
    float acc = 0.0f;
#pragma unroll
    for (int c = 0; c < DCHUNKS; c++) acc += g_vpart[c * H + h];
    g_v[h] = acc;
}

// ---------------------------------------------------------------------------
// scores[s] = enc[s] . v      (the 128 MB HBM-bound pass — near roofline)
// 8 warps/block, 1 row/warp, v staged in shared. grid 4096, block 256.
// ---------------------------------------------------------------------------
__global__ void k_scores(const float* __restrict__ enc) {
    __shared__ float4 sv[H / 4];   // 4 KB
    const int tid  = threadIdx.x;
    const int warp = tid >> 5;
    const int lane = tid & 31;

    sv[tid] = reinterpret_cast<const float4*>(g_v)[tid];
    __syncthreads();

    const int row = blockIdx.x * 8 + warp;
    const float4* erow = reinterpret_cast<const float4*>(enc + (size_t)row * H);

    float acc = 0.0f;
#pragma unroll
    for (int i = 0; i < 8; i++) {
        const int idx = lane + 32 * i;
        float4 e = __ldg(&erow[idx]);
        float4 w = sv[idx];
        acc = fmaf(e.x, w.x, acc);
        acc = fmaf(e.y, w.y, acc);
        acc = fmaf(e.z, w.z, acc);
        acc = fmaf(e.w, w.w, acc);
    }
#pragma unroll
    for (int off = 16; off > 0; off >>= 1)
        acc += __shfl_xor_sync(0xFFFFFFFFu, acc, off);
    if (lane == 0) g_scores[row] = acc;
}

// ---------------------------------------------------------------------------
// Per-block softmax partials: (max_b, sum_b = sum exp(s - max_b)).
// grid NPART=32 blocks x 512 threads; each block owns 1024 contiguous scores.
// One pass (merge identity fixes up sums later).
// ---------------------------------------------------------------------------
__global__ void k_stats_partial() {
    __shared__ float red[512];
    const int t = threadIdx.x;
    const float* s = g_scores + blockIdx.x * 1024;

    float a = s[t], c = s[t + 512];
    red[t] = fmaxf(a, c);
    __syncthreads();
#pragma unroll
    for (int k = 256; k > 0; k >>= 1) {
        if (t < k) red[t] = fmaxf(red[t], red[t + k]);
        __syncthreads();
    }
    const float bm = red[0];
    __syncthreads();

    red[t] = __expf(a - bm) + __expf(c - bm);
    __syncthreads();
#pragma unroll
    for (int k = 256; k > 0; k >>= 1) {
        if (t < k) red[t] += red[t + k];
        __syncthreads();
    }
    if (t == 0) {
        g_pmax[blockIdx.x] = bm;
        g_psum[blockIdx.x] = red[0];
    }
}

// ---------------------------------------------------------------------------
// Fused combine + normalize. Each block re-derives (gmax, inv_sum) from the
// 32 partial pairs (L2-hit, ~free), then writes float4 outputs.
// grid 64, block 128 (128 threads x 4 floats x 64 blocks = 32768).
// ---------------------------------------------------------------------------
__global__ void k_norm(float* __restrict__ out) {
    __shared__ float sh[2];
    const int t = threadIdx.x;

    if (t < 32) {
        float pm = g_pmax[t];
        float gmax = pm;
#pragma unroll
        for (int off = 16; off > 0; off >>= 1)
            gmax = fmaxf(gmax, __shfl_xor_sync(0xFFFFFFFFu, gmax, off));
        float ps = g_psum[t] * __expf(pm - gmax);
#pragma unroll
        for (int off = 16; off > 0; off >>= 1)
            ps += __shfl_xor_sync(0xFFFFFFFFu, ps, off);
        if (t == 0) { sh[0] = gmax; sh[1] = 1.0f / ps; }
    }
    __syncthreads();
    const float gmax = sh[0], inv = sh[1];

    const int i = blockIdx.x * 128 + t;
    float4 sc = reinterpret_cast<const float4*>(g_scores)[i];
    float4 o;
    o.x = __expf(sc.x - gmax) * inv;
    o.y = __expf(sc.y - gmax) * inv;
    o.z = __expf(sc.z - gmax) * inv;
    o.w = __expf(sc.w - gmax) * inv;
    reinterpret_cast<float4*>(out)[i] = o;
}

// ---------------------------------------------------------------------------
// Inputs: hidden[1024], encoder_outputs[32768*1024], W[1024*1024], b[1024]
// (b cancels in softmax). Output: float[32768].
// ---------------------------------------------------------------------------
extern "C" void kernel_launch(void* const* d_in, const int* in_sizes, int n_in,
                              void* d_out, int out_size) {
    const float* hidden = (const float*)d_in[0];
    const float* enc    = (const float*)d_in[1];
    const float* W      = (const float*)d_in[2];
    float* out          = (float*)d_out;

    dim3 g1(H / 128, DCHUNKS);
    k_matvec_partial<<<g1, 128>>>(hidden, W);
    k_matvec_reduce<<<H / 256, 256>>>();
    k_scores<<<S / 8, 256>>>(enc);
    k_stats_partial<<<NPART, 512>>>();
    k_norm<<<S / (128 * 4), 128>>>(out);
}

// round 3
// speedup vs baseline: 1.1152x; 1.0081x over previous
#include <cuda_runtime.h>
#include <math.h>

#define H 1024
#define S 32768
#define DCHUNKS 32
#define DPER (H / DCHUNKS)        // 32
#define NBLK (S / 8)              // 4096 scores blocks -> 4096 partial pairs

// Scratch (no allocations allowed in kernel_launch)
__device__ __align__(16) float g_vpart[DCHUNKS * H];
__device__ __align__(16) float g_v[H];
__device__ __align__(16) float g_scores[S];
__device__ __align__(16) float g_pmax[NBLK];
__device__ __align__(16) float g_psum[NBLK];

// ---------------------------------------------------------------------------
// v_partial[chunk][h] = sum_{d in chunk} hidden[d] * W[d*H + h]
// grid (H/128, DCHUNKS), block 128.
// ---------------------------------------------------------------------------
__global__ void k_matvec_partial(const float* __restrict__ hidden,
                                 const float* __restrict__ W) {
    const int h     = blockIdx.x * 128 + threadIdx.x;
    const int chunk = blockIdx.y;
    const int d0    = chunk * DPER;
    float acc = 0.0f;
#pragma unroll 8
    for (int d = 0; d < DPER; d++) {
        acc = fmaf(__ldg(&hidden[d0 + d]), __ldg(&W[(size_t)(d0 + d) * H + h]), acc);
    }
    g_vpart[chunk * H + h] = acc;
}

// ---------------------------------------------------------------------------
// v[h] = deterministic fold over chunks. grid 4, block 256.
// ---------------------------------------------------------------------------
__global__ void k_matvec_reduce() {
    const int h = blockIdx.x * 256 + threadIdx.x;
    float acc = 0.0f;
#pragma unroll
    for (int c = 0; c < DCHUNKS; c++) acc += g_vpart[c * H + h];
    g_v[h] = acc;
}

// ---------------------------------------------------------------------------
// scores[s] = enc[s] . v   (the 128 MB HBM-bound pass — near roofline)
// 8 warps/block, 1 row/warp, v staged in shared. grid 4096, block 256.
// FUSED TAIL: warp 0 reduces the block's 8 scores to (max, sum exp(s-max))
// and writes one partial pair — replaces the standalone stats kernel.
// ---------------------------------------------------------------------------
__global__ void k_scores(const float* __restrict__ enc) {
    __shared__ float4 sv[H / 4];   // 4 KB
    __shared__ float srow[8];
    const int tid  = threadIdx.x;
    const int warp = tid >> 5;
    const int lane = tid & 31;

    sv[tid] = reinterpret_cast<const float4*>(g_v)[tid];
    __syncthreads();

    const int row = blockIdx.x * 8 + warp;
    const float4* erow = reinterpret_cast<const float4*>(enc + (size_t)row * H);

    float acc = 0.0f;
#pragma unroll
    for (int i = 0; i < 8; i++) {
        const int idx = lane + 32 * i;
        float4 e = __ldg(&erow[idx]);
        float4 w = sv[idx];
        acc = fmaf(e.x, w.x, acc);
        acc = fmaf(e.y, w.y, acc);
        acc = fmaf(e.z, w.z, acc);
        acc = fmaf(e.w, w.w, acc);
    }
#pragma unroll
    for (int off = 16; off > 0; off >>= 1)
        acc += __shfl_xor_sync(0xFFFFFFFFu, acc, off);
    if (lane == 0) {
        g_scores[row] = acc;
        srow[warp]    = acc;
    }
    __syncthreads();

    // warp 0: partial softmax stats over this block's 8 scores
    if (warp == 0) {
        float s = (lane < 8) ? srow[lane] : -INFINITY;
        float m = s;
#pragma unroll
        for (int off = 4; off > 0; off >>= 1)
            m = fmaxf(m, __shfl_xor_sync(0xFFFFFFFFu, m, off));
        m = __shfl_sync(0xFFFFFFFFu, m, 0, 8);
        float e = (lane < 8) ? __expf(s - m) : 0.0f;
#pragma unroll
        for (int off = 4; off > 0; off >>= 1)
            e += __shfl_xor_sync(0xFFFFFFFFu, e, off);
        if (lane == 0) {
            g_pmax[blockIdx.x] = m;
            g_psum[blockIdx.x] = e;
        }
    }
}

// ---------------------------------------------------------------------------
// Fused combine + normalize. Each block re-derives (gmax, inv_sum) from the
// 4096 partial pairs via the merge identity (warp shuffles, 2 barriers),
// then writes float4 outputs. grid 64, block 128.
// ---------------------------------------------------------------------------
__global__ void k_norm(float* __restrict__ out) {
    __shared__ float wred[4];
    __shared__ float sh[2];
    const int t    = threadIdx.x;
    const int warp = t >> 5;
    const int lane = t & 31;

    // Pass 1: global max over 4096 pmax (each thread strides 32 values)
    float m = -INFINITY;
#pragma unroll
    for (int j = 0; j < NBLK / 128; j++)
        m = fmaxf(m, g_pmax[t + 128 * j]);
#pragma unroll
    for (int off = 16; off > 0; off >>= 1)
        m = fmaxf(m, __shfl_xor_sync(0xFFFFFFFFu, m, off));
    if (lane == 0) wred[warp] = m;
    __syncthreads();
    float gmax = fmaxf(fmaxf(wred[0], wred[1]), fmaxf(wred[2], wred[3]));

    // Pass 2: merged sum  Σ psum_b * exp(pmax_b - gmax)
    float sum = 0.0f;
#pragma unroll
    for (int j = 0; j < NBLK / 128; j++) {
        const int i = t + 128 * j;
        sum = fmaf(g_psum[i], __expf(g_pmax[i] - gmax), sum);
    }
#pragma unroll
    for (int off = 16; off > 0; off >>= 1)
        sum += __shfl_xor_sync(0xFFFFFFFFu, sum, off);
    __syncthreads();
    if (lane == 0) wred[warp] = sum;
    __syncthreads();
    if (t == 0) {
        sh[0] = gmax;
        sh[1] = 1.0f / (wred[0] + wred[1] + wred[2] + wred[3]);
    }
    __syncthreads();
    gmax = sh[0];
    const float inv = sh[1];

    const int i = blockIdx.x * 128 + t;
    float4 sc = reinterpret_cast<const float4*>(g_scores)[i];
    float4 o;
    o.x = __expf(sc.x - gmax) * inv;
    o.y = __expf(sc.y - gmax) * inv;
    o.z = __expf(sc.z - gmax) * inv;
    o.w = __expf(sc.w - gmax) * inv;
    reinterpret_cast<float4*>(out)[i] = o;
}

// ---------------------------------------------------------------------------
// Inputs: hidden[1024], encoder_outputs[32768*1024], W[1024*1024], b[1024]
// (b cancels in softmax). Output: float[32768].
// ---------------------------------------------------------------------------
extern "C" void kernel_launch(void* const* d_in, const int* in_sizes, int n_in,
                              void* d_out, int out_size) {
    const float* hidden = (const float*)d_in[0];
    const float* enc    = (const float*)d_in[1];
    const float* W      = (const float*)d_in[2];
    float* out          = (float*)d_out;

    dim3 g1(H / 128, DCHUNKS);
    k_matvec_partial<<<g1, 128>>>(hidden, W);
    k_matvec_reduce<<<H / 256, 256>>>();
    k_scores<<<S / 8, 256>>>(enc);
    k_norm<<<S / (128 * 4), 128>>>(out);
}

// round 6
// speedup vs baseline: 1.1223x; 1.0063x over previous
#include <cuda_runtime.h>
#include <math.h>

#define H 1024
#define S 32768
#define DCHUNKS 32
#define DPER (H / DCHUNKS)        // 32
#define NBLK (S / 8)              // 4096 scores blocks -> 4096 partial pairs

// Scratch (no allocations allowed in kernel_launch)
__device__ __align__(16) float g_vpart[DCHUNKS * H];
__device__ __align__(16) float g_v[H];
__device__ __align__(16) float g_scores[S];
__device__ __align__(16) float g_pmax[NBLK];
__device__ __align__(16) float g_psum[NBLK];
__device__ __align__(16) float g_stats[2];   // {gmax, inv_sum}

// ---------------------------------------------------------------------------
// v_partial[chunk][h] = sum_{d in chunk} hidden[d] * W[d*H + h]
// grid (H/128, DCHUNKS), block 128.
// ---------------------------------------------------------------------------
__global__ void k_matvec_partial(const float* __restrict__ hidden,
                                 const float* __restrict__ W) {
    const int h     = blockIdx.x * 128 + threadIdx.x;
    const int chunk = blockIdx.y;
    const int d0    = chunk * DPER;
    float acc = 0.0f;
#pragma unroll 8
    for (int d = 0; d < DPER; d++) {
        acc = fmaf(__ldg(&hidden[d0 + d]), __ldg(&W[(size_t)(d0 + d) * H + h]), acc);
    }
    g_vpart[chunk * H + h] = acc;
}

// ---------------------------------------------------------------------------
// v[h] = deterministic fold over chunks. grid 4, block 256.
// ---------------------------------------------------------------------------
__global__ void k_matvec_reduce() {
    const int h = blockIdx.x * 256 + threadIdx.x;
    float acc = 0.0f;
#pragma unroll
    for (int c = 0; c < DCHUNKS; c++) acc += g_vpart[c * H + h];
    g_v[h] = acc;
}

// ---------------------------------------------------------------------------
// scores[s] = enc[s] . v   (the 128 MB HBM-bound pass — near roofline)
// 8 warps/block, 1 row/warp, v staged in shared. grid 4096, block 256.
// Fused tail: warp 0 writes this block's (max, sum exp(s-max)) partial pair.
// ---------------------------------------------------------------------------
__global__ void k_scores(const float* __restrict__ enc) {
    __shared__ float4 sv[H / 4];   // 4 KB
    __shared__ float srow[8];
    const int tid  = threadIdx.x;
    const int warp = tid >> 5;
    const int lane = tid & 31;

    sv[tid] = reinterpret_cast<const float4*>(g_v)[tid];
    __syncthreads();

    const int row = blockIdx.x * 8 + warp;
    const float4* erow = reinterpret_cast<const float4*>(enc + (size_t)row * H);

    float acc = 0.0f;
#pragma unroll
    for (int i = 0; i < 8; i++) {
        const int idx = lane + 32 * i;
        float4 e = __ldg(&erow[idx]);
        float4 w = sv[idx];
        acc = fmaf(e.x, w.x, acc);
        acc = fmaf(e.y, w.y, acc);
        acc = fmaf(e.z, w.z, acc);
        acc = fmaf(e.w, w.w, acc);
    }
#pragma unroll
    for (int off = 16; off > 0; off >>= 1)
        acc += __shfl_xor_sync(0xFFFFFFFFu, acc, off);
    if (lane == 0) {
        g_scores[row] = acc;
        srow[warp]    = acc;
    }
    __syncthreads();

    if (warp == 0) {
        float s = (lane < 8) ? srow[lane] : -INFINITY;
        float m = s;
#pragma unroll
        for (int off = 4; off > 0; off >>= 1)
            m = fmaxf(m, __shfl_xor_sync(0xFFFFFFFFu, m, off));
        m = __shfl_sync(0xFFFFFFFFu, m, 0, 8);
        float e = (lane < 8) ? __expf(s - m) : 0.0f;
#pragma unroll
        for (int off = 4; off > 0; off >>= 1)
            e += __shfl_xor_sync(0xFFFFFFFFu, e, off);
        if (lane == 0) {
            g_pmax[blockIdx.x] = m;
            g_psum[blockIdx.x] = e;
        }
    }
}

// ---------------------------------------------------------------------------
// Combine 4096 partial pairs -> (gmax, inv_sum), ONCE. 1 block, 1024 threads.
// Merge identity: sum = Σ psum_b * exp(pmax_b - gmax).
// ---------------------------------------------------------------------------
__global__ void k_combine() {
    __shared__ float wred[32];
    const int t    = threadIdx.x;
    const int warp = t >> 5;
    const int lane = t & 31;

    float pm[4], ps[4];
#pragma unroll
    for (int j = 0; j < 4; j++) {
        pm[j] = g_pmax[t + 1024 * j];
        ps[j] = g_psum[t + 1024 * j];
    }
    float m = fmaxf(fmaxf(pm[0], pm[1]), fmaxf(pm[2], pm[3]));
#pragma unroll
    for (int off = 16; off > 0; off >>= 1)
        m = fmaxf(m, __shfl_xor_sync(0xFFFFFFFFu, m, off));
    if (lane == 0) wred[warp] = m;
    __syncthreads();
    if (warp == 0) {
        float mm = wred[lane];
#pragma unroll
        for (int off = 16; off > 0; off >>= 1)
            mm = fmaxf(mm, __shfl_xor_sync(0xFFFFFFFFu, mm, off));
        if (lane == 0) wred[0] = mm;
    }
    __syncthreads();
    const float gmax = wred[0];
    __syncthreads();

    float sum = 0.0f;
#pragma unroll
    for (int j = 0; j < 4; j++)
        sum = fmaf(ps[j], __expf(pm[j] - gmax), sum);
#pragma unroll
    for (int off = 16; off > 0; off >>= 1)
        sum += __shfl_xor_sync(0xFFFFFFFFu, sum, off);
    if (lane == 0) wred[warp] = sum;
    __syncthreads();
    if (t == 0) {
        float tot = 0.0f;
#pragma unroll
        for (int w = 0; w < 32; w++) tot += wred[w];
        g_stats[0] = gmax;
        g_stats[1] = 1.0f / tot;
    }
}

// ---------------------------------------------------------------------------
// Pure streaming normalize: out = exp(s - gmax) * inv.  grid 64, block 128.
// ---------------------------------------------------------------------------
__global__ void k_norm(float* __restrict__ out) {
    const float gmax = g_stats[0];
    const float inv  = g_stats[1];
    const int i = blockIdx.x * 128 + threadIdx.x;
    float4 sc = reinterpret_cast<const float4*>(g_scores)[i];
    float4 o;
    o.x = __expf(sc.x - gmax) * inv;
    o.y = __expf(sc.y - gmax) * inv;
    o.z = __expf(sc.z - gmax) * inv;
    o.w = __expf(sc.w - gmax) * inv;
    reinterpret_cast<float4*>(out)[i] = o;
}

// ---------------------------------------------------------------------------
// Inputs: hidden[1024], encoder_outputs[32768*1024], W[1024*1024], b[1024]
// (b cancels in softmax). Output: float[32768].
// ---------------------------------------------------------------------------
extern "C" void kernel_launch(void* const* d_in, const int* in_sizes, int n_in,
                              void* d_out, int out_size) {
    const float* hidden = (const float*)d_in[0];
    const float* enc    = (const float*)d_in[1];
    const float* W      = (const float*)d_in[2];
    float* out          = (float*)d_out;

    dim3 g1(H / 128, DCHUNKS);
    k_matvec_partial<<<g1, 128>>>(hidden, W);
    k_matvec_reduce<<<H / 256, 256>>>();
    k_scores<<<S / 8, 256>>>(enc);
    k_combine<<<1, 1024>>>();
    k_norm<<<S / (128 * 4), 128>>>(out);
}

// round 7
// speedup vs baseline: 1.1264x; 1.0036x over previous
#include <cuda_runtime.h>
#include <math.h>

#define H 1024
#define S 32768
#define NBLOCK 148
#define NTHREAD 1024
#define NWARP 32
#define GWARPS (NBLOCK * NWARP)          // 4736
#define NF4 (S / 4)                      // 8192 output float4s

// Scratch (no allocations allowed in kernel_launch)
__device__ __align__(16) float g_v[H];
__device__ __align__(16) float g_scores[S];
__device__ __align__(16) float g_pmax[NBLOCK];
__device__ __align__(16) float g_psum[NBLOCK];

// Grid barrier state: counters self-reset, epoch flags are monotonic so they
// are correct across CUDA-graph replays of the same kernel.
__device__ unsigned g_cnt[2];
__device__ unsigned g_flag[2];

__device__ __forceinline__ void grid_bar(int i) {
    __syncthreads();
    if (threadIdx.x == 0) {
        volatile unsigned* flag = &g_flag[i];
        unsigned snap = *flag;
        __threadfence();
        unsigned pos = atomicAdd(&g_cnt[i], 1u);
        if (pos == NBLOCK - 1) {
            g_cnt[i] = 0;               // all arrivals done; safe to reset
            __threadfence();
            atomicAdd(&g_flag[i], 1u);  // release (monotonic epoch)
        } else {
            while (*flag == snap) { __nanosleep(64); }
        }
        __threadfence();
    }
    __syncthreads();
}

__global__ __launch_bounds__(NTHREAD, 1)
void k_all(const float* __restrict__ hidden,
           const float* __restrict__ enc,
           const float* __restrict__ W,
           float* __restrict__ out) {
    __shared__ float  ph1[33 * 32];     // phase-1 partials (padded: no bank conflicts)
    __shared__ float4 sv[H / 4];        // v staged for scores
    __shared__ float  sm[NWARP], ss[NWARP];
    __shared__ float  sh[2];

    const int b    = blockIdx.x;
    const int t    = threadIdx.x;
    const int warp = t >> 5;
    const int lane = t & 31;

    // ---------------- Phase 1: v = W^T-applied matvec (32 blocks) -------------
    // block b<32 owns h-range [b*32, b*32+32); thread: hh = t&31, dgroup = t>>5
    if (b < 32) {
        const int h0 = b * 32;
        const int hh = lane;
        const int dg = warp;            // 32 d-groups of 32
        float acc = 0.0f;
#pragma unroll 8
        for (int j = 0; j < 32; j++) {
            const int d = dg * 32 + j;
            acc = fmaf(__ldg(&hidden[d]), __ldg(&W[(size_t)d * H + h0 + hh]), acc);
        }
        ph1[dg * 33 + hh] = acc;
        __syncthreads();
        if (t < 32) {
            float v = 0.0f;
#pragma unroll
            for (int dgi = 0; dgi < 32; dgi++) v += ph1[dgi * 33 + t];
            g_v[h0 + t] = v;
        }
    }

    grid_bar(0);

    // ---------------- Phase 2: scores + online softmax partials ---------------
    if (t < H / 4) sv[t] = reinterpret_cast<const float4*>(g_v)[t];
    __syncthreads();

    const int gwarp = b * NWARP + warp;
    float m = -INFINITY, s = 0.0f;

#pragma unroll 1
    for (int it = 0; it < 7; it++) {
        const int row = it * GWARPS + gwarp;
        if (row >= S) break;
        const float4* erow = reinterpret_cast<const float4*>(enc + (size_t)row * H);
        float acc = 0.0f;
#pragma unroll
        for (int i = 0; i < 8; i++) {
            const int idx = lane + 32 * i;
            float4 e = __ldg(&erow[idx]);
            float4 w = sv[idx];
            acc = fmaf(e.x, w.x, acc);
            acc = fmaf(e.y, w.y, acc);
            acc = fmaf(e.z, w.z, acc);
            acc = fmaf(e.w, w.w, acc);
        }
#pragma unroll
        for (int off = 16; off > 0; off >>= 1)
            acc += __shfl_xor_sync(0xFFFFFFFFu, acc, off);
        if (lane == 0) g_scores[row] = acc;
        // online stats (all lanes redundantly; deterministic)
        const float mn = fmaxf(m, acc);
        s = s * __expf(m - mn) + __expf(acc - mn);
        m = mn;
    }
    if (lane == 0) { sm[warp] = m; ss[warp] = s; }
    __syncthreads();

    if (warp == 0) {
        float wm = sm[lane], wsum = ss[lane];
        float gm = wm;
#pragma unroll
        for (int off = 16; off > 0; off >>= 1)
            gm = fmaxf(gm, __shfl_xor_sync(0xFFFFFFFFu, gm, off));
        float e = wsum * __expf(wm - gm);
#pragma unroll
        for (int off = 16; off > 0; off >>= 1)
            e += __shfl_xor_sync(0xFFFFFFFFu, e, off);
        if (lane == 0) { g_pmax[b] = gm; g_psum[b] = e; }
    }

    grid_bar(1);

    // ---------------- Phase 3: redundant combine (148 pairs) + normalize ------
    if (warp == 0) {
        float lm = -INFINITY, lsum = 0.0f;
        float pm[5], psv[5];
#pragma unroll
        for (int j = 0; j < 5; j++) {
            const int idx = lane + 32 * j;
            const bool ok = idx < NBLOCK;
            pm[j]  = ok ? g_pmax[idx] : -INFINITY;
            psv[j] = ok ? g_psum[idx] : 0.0f;
            lm = fmaxf(lm, pm[j]);
        }
        float gm = lm;
#pragma unroll
        for (int off = 16; off > 0; off >>= 1)
            gm = fmaxf(gm, __shfl_xor_sync(0xFFFFFFFFu, gm, off));
#pragma unroll
        for (int j = 0; j < 5; j++)
            lsum = fmaf(psv[j], __expf(pm[j] - gm), lsum);
#pragma unroll
        for (int off = 16; off > 0; off >>= 1)
            lsum += __shfl_xor_sync(0xFFFFFFFFu, lsum, off);
        if (lane == 0) { sh[0] = gm; sh[1] = 1.0f / lsum; }
    }
    __syncthreads();
    const float gmax = sh[0], inv = sh[1];

    // contiguous per-block slice of the 8192 output float4s
    const unsigned s0 = ((unsigned)b * NF4) / NBLOCK;
    const unsigned s1 = ((unsigned)(b + 1) * NF4) / NBLOCK;
    const unsigned i  = s0 + t;
    if (i < s1) {
        float4 sc = reinterpret_cast<const float4*>(g_scores)[i];
        float4 o;
        o.x = __expf(sc.x - gmax) * inv;
        o.y = __expf(sc.y - gmax) * inv;
        o.z = __expf(sc.z - gmax) * inv;
        o.w = __expf(sc.w - gmax) * inv;
        reinterpret_cast<float4*>(out)[i] = o;
    }
}

// ---------------------------------------------------------------------------
// Inputs: hidden[1024], encoder_outputs[32768*1024], W[1024*1024], b[1024]
// (b cancels in softmax). Output: float[32768].
// ---------------------------------------------------------------------------
extern "C" void kernel_launch(void* const* d_in, const int* in_sizes, int n_in,
                              void* d_out, int out_size) {
    const float* hidden = (const float*)d_in[0];
    const float* enc    = (const float*)d_in[1];
    const float* W      = (const float*)d_in[2];
    float* out          = (float*)d_out;

    k_all<<<NBLOCK, NTHREAD>>>(hidden, enc, W, out);
}